// round 5
// baseline (speedup 1.0000x reference)
#include <cuda_runtime.h>
#include <cuda_bf16.h>
#include <math.h>

#define T_ 32
#define B_ 64
#define S_ 64
#define D_ 1024
#define D4_ 4096
#define TB_ 2048

// ---------------- scratch (device globals) ----------------
__device__ float g_xg[TB_ * D4_];     // input-gate GEMM output (fp32)
__device__ float g_x1[TB_ * D_];      // layer0 h fp32
__device__ float g_x2[TB_ * D_];      // layer1 h fp32
__device__ float g_c [B_ * D_];
__device__ float g_q [TB_ * D_];

__device__ __align__(16) __nv_bfloat16 g_x0h[TB_ * D_], g_x0l[TB_ * D_];
__device__ __align__(16) __nv_bfloat16 g_sh [TB_ * D_], g_sl [TB_ * D_];   // h sequence hi/lo
__device__ __align__(16) __nv_bfloat16 g_h0h[B_ * D_],  g_h0l[B_ * D_];
__device__ __align__(16) __nv_bfloat16 g_cath[TB_ * 2 * D_], g_catl[TB_ * 2 * D_];

__device__ __align__(16) __nv_bfloat16 g_whhh0[D4_ * D_], g_whhl0[D4_ * D_];
__device__ __align__(16) __nv_bfloat16 g_whhh1[D4_ * D_], g_whhl1[D4_ * D_];
__device__ __align__(16) __nv_bfloat16 g_wihh0[D4_ * D_], g_wihl0[D4_ * D_];
__device__ __align__(16) __nv_bfloat16 g_wihh1[D4_ * D_], g_wihl1[D4_ * D_];
__device__ __align__(16) __nv_bfloat16 g_winh[D_ * D_],   g_winl[D_ * D_];
__device__ __align__(16) __nv_bfloat16 g_wouth[D_ * 2 * D_], g_woutl[D_ * 2 * D_];

// ---------------- helpers ----------------
__device__ __forceinline__ void mma16816(float* d, const unsigned* a, const unsigned* b)
{
    asm volatile(
        "mma.sync.aligned.m16n8k16.row.col.f32.bf16.bf16.f32 "
        "{%0,%1,%2,%3}, {%4,%5,%6,%7}, {%8,%9}, {%0,%1,%2,%3};"
        : "+f"(d[0]), "+f"(d[1]), "+f"(d[2]), "+f"(d[3])
        : "r"(a[0]), "r"(a[1]), "r"(a[2]), "r"(a[3]),
          "r"(b[0]), "r"(b[1]));
}

// split float4 into bf16 hi pair2 + lo pair2
__device__ __forceinline__ void split_store4(float4 v,
                                             __nv_bfloat162* hp,
                                             __nv_bfloat162* lp)
{
    float hx = __bfloat162float(__float2bfloat16(v.x));
    float hy = __bfloat162float(__float2bfloat16(v.y));
    float hz = __bfloat162float(__float2bfloat16(v.z));
    float hw = __bfloat162float(__float2bfloat16(v.w));
    hp[0] = __nv_bfloat162(__float2bfloat16(hx), __float2bfloat16(hy));
    hp[1] = __nv_bfloat162(__float2bfloat16(hz), __float2bfloat16(hw));
    lp[0] = __nv_bfloat162(__float2bfloat16(v.x - hx), __float2bfloat16(v.y - hy));
    lp[1] = __nv_bfloat162(__float2bfloat16(v.z - hz), __float2bfloat16(v.w - hw));
}

// ---------------- split fp32 -> bf16 hi + lo ----------------
__global__ void split_kernel(const float* __restrict__ w,
                             __nv_bfloat16* __restrict__ hi,
                             __nv_bfloat16* __restrict__ lo, int n4)
{
    int i = blockIdx.x * blockDim.x + threadIdx.x;
    if (i >= n4) return;
    float4 v = ((const float4*)w)[i];
    split_store4(v, (__nv_bfloat162*)hi + i * 2, (__nv_bfloat162*)lo + i * 2);
}

// ---------------- embedding -> bf16 hi/lo (padding_idx = 0) ----------------
__global__ void embed_kernel(const int* __restrict__ tok,
                             const float* __restrict__ emb,
                             __nv_bfloat16* __restrict__ xh,
                             __nv_bfloat16* __restrict__ xl)
{
    int tb = blockIdx.x;
    int t4 = threadIdx.x;       // 0..255
    int tk = tok[tb];
    float4 v = make_float4(0.f, 0.f, 0.f, 0.f);
    if (tk != 0) v = ((const float4*)(emb + (size_t)tk * D_))[t4];
    split_store4(v, (__nv_bfloat162*)(xh + (size_t)tb * D_) + t4 * 2,
                    (__nv_bfloat162*)(xl + (size_t)tb * D_) + t4 * 2);
}

// ---------------- bf16 tensor GEMM: C = A @ B^T, 3-term compensated ----------
// A: (M,K) bf16 hi/lo row-major; B: (N,K) bf16 hi/lo row-major; C fp32 (M,N).
// block = 128x128, 8 warps (2x4), warp tile 64x32.
// EPI: 0 none, 1 +bias1[n]+bias2[n], 2 tanh
template<int EPI>
__global__ __launch_bounds__(256)
void hgemm_nt(const __nv_bfloat16* __restrict__ Ahi,
              const __nv_bfloat16* __restrict__ Alo,
              const __nv_bfloat16* __restrict__ Bhi,
              const __nv_bfloat16* __restrict__ Blo,
              float* __restrict__ C, int M, int N, int K,
              const float* __restrict__ bias1, const float* __restrict__ bias2)
{
    const int tid  = threadIdx.x;
    const int wid  = tid >> 5;
    const int lane = tid & 31;
    const int gid  = lane >> 2;      // 0..7
    const int tig  = lane & 3;       // 0..3
    const int wm   = wid >> 2;       // 0..1
    const int wn   = wid & 3;        // 0..3
    const int bm   = blockIdx.y * 128;
    const int bn   = blockIdx.x * 128;
    const int strd = K >> 1;         // u32 per row
    const int K16  = K >> 4;

    float acc[4][4][4];
#pragma unroll
    for (int mt = 0; mt < 4; mt++)
#pragma unroll
        for (int nt = 0; nt < 4; nt++)
#pragma unroll
            for (int r = 0; r < 4; r++) acc[mt][nt][r] = 0.f;

    const unsigned* As[3] = { (const unsigned*)Ahi, (const unsigned*)Alo,
                              (const unsigned*)Ahi };
    const unsigned* Bs[3] = { (const unsigned*)Bhi, (const unsigned*)Bhi,
                              (const unsigned*)Blo };

#pragma unroll 1
    for (int p = 0; p < 3; p++) {
        const unsigned* A = As[p];
        const unsigned* B = Bs[p];
#pragma unroll 2
        for (int k16 = 0; k16 < K16; k16++) {
            const int kc = (k16 << 3) + tig;
            unsigned a[4][4], b[4][2];
#pragma unroll
            for (int mt = 0; mt < 4; mt++) {
                int row = bm + (wm << 6) + (mt << 4) + gid;
                const unsigned* pa = A + (size_t)row * strd + kc;
                a[mt][0] = __ldg(pa);
                a[mt][1] = __ldg(pa + (size_t)8 * strd);
                a[mt][2] = __ldg(pa + 4);
                a[mt][3] = __ldg(pa + (size_t)8 * strd + 4);
            }
#pragma unroll
            for (int nt = 0; nt < 4; nt++) {
                int row = bn + (wn << 5) + (nt << 3) + gid;
                const unsigned* pb = B + (size_t)row * strd + kc;
                b[nt][0] = __ldg(pb);
                b[nt][1] = __ldg(pb + 4);
            }
#pragma unroll
            for (int mt = 0; mt < 4; mt++)
#pragma unroll
                for (int nt = 0; nt < 4; nt++)
                    mma16816(acc[mt][nt], a[mt], b[nt]);
        }
    }

    // epilogue
#pragma unroll
    for (int mt = 0; mt < 4; mt++)
#pragma unroll
        for (int nt = 0; nt < 4; nt++)
#pragma unroll
            for (int rp = 0; rp < 2; rp++) {
                int row = bm + (wm << 6) + (mt << 4) + gid + (rp << 3);
                int col = bn + (wn << 5) + (nt << 3) + (tig << 1);
                float v0 = acc[mt][nt][rp * 2];
                float v1 = acc[mt][nt][rp * 2 + 1];
                if (EPI == 1) {
                    v0 += __ldg(bias1 + col) + __ldg(bias2 + col);
                    v1 += __ldg(bias1 + col + 1) + __ldg(bias2 + col + 1);
                }
                if (EPI == 2) { v0 = tanhf(v0); v1 = tanhf(v1); }
                float2 o; o.x = v0; o.y = v1;
                *(float2*)(C + (size_t)row * N + col) = o;
            }
}

// ---------------- LSTM step via bf16 mma, 3-term split ----------------
__global__ __launch_bounds__(256, 1)
void lstm_step_mma(const __nv_bfloat16* __restrict__ hA_hi,
                   const __nv_bfloat16* __restrict__ hA_lo,
                   const __nv_bfloat16* __restrict__ w_hi,
                   const __nv_bfloat16* __restrict__ w_lo,
                   const float* __restrict__ xg_t,   // (B, 4D)
                   float* __restrict__ c,            // (B, D)
                   float* __restrict__ hout,         // (B, D)
                   __nv_bfloat16* __restrict__ hN_hi,
                   __nv_bfloat16* __restrict__ hN_lo)
{
    __shared__ float red[4][2112];

    const int tid  = threadIdx.x;
    const int wid  = tid >> 5;
    const int lane = tid & 31;
    const int gid  = lane >> 2;
    const int tig  = lane & 3;
    const int d0   = blockIdx.x << 3;

    float acc[4][4][4];
#pragma unroll
    for (int mt = 0; mt < 4; mt++)
#pragma unroll
        for (int g = 0; g < 4; g++)
#pragma unroll
            for (int r = 0; r < 4; r++) acc[mt][g][r] = 0.f;

    const unsigned* Hs[3] = { (const unsigned*)hA_hi, (const unsigned*)hA_lo,
                              (const unsigned*)hA_hi };
    const unsigned* Ws[3] = { (const unsigned*)w_hi, (const unsigned*)w_hi,
                              (const unsigned*)w_lo };
    const int kw = wid << 7;

#pragma unroll
    for (int p = 0; p < 3; p++) {
        const unsigned* H = Hs[p];
        const unsigned* W = Ws[p];
#pragma unroll
        for (int s = 0; s < 8; s++) {
            const int kc = (kw + s * 16 + tig * 2) >> 1;
            unsigned a[4][4], b[4][2];
#pragma unroll
            for (int mt = 0; mt < 4; mt++) {
                int r0 = ((mt << 4) + gid) << 9;
                a[mt][0] = __ldg(H + r0 + kc);
                a[mt][1] = __ldg(H + r0 + (8 << 9) + kc);
                a[mt][2] = __ldg(H + r0 + kc + 4);
                a[mt][3] = __ldg(H + r0 + (8 << 9) + kc + 4);
            }
#pragma unroll
            for (int g = 0; g < 4; g++) {
                int rn = ((g << 10) + d0 + gid) << 9;
                b[g][0] = __ldg(W + rn + kc);
                b[g][1] = __ldg(W + rn + kc + 4);
            }
#pragma unroll
            for (int mt = 0; mt < 4; mt++)
#pragma unroll
                for (int g = 0; g < 4; g++)
                    mma16816(acc[mt][g], a[mt], b[g]);
        }
    }

    // ---- tree reduction across 8 warps ----
    if (wid >= 4) {
#pragma unroll
        for (int mt = 0; mt < 4; mt++)
#pragma unroll
            for (int g = 0; g < 4; g++)
#pragma unroll
                for (int r = 0; r < 4; r++)
                    red[wid - 4][((mt << 4) + (g << 2) + r) * 32 + lane] = acc[mt][g][r];
    }
    __syncthreads();
    if (wid < 4) {
#pragma unroll
        for (int mt = 0; mt < 4; mt++)
#pragma unroll
            for (int g = 0; g < 4; g++)
#pragma unroll
                for (int r = 0; r < 4; r++)
                    acc[mt][g][r] += red[wid][((mt << 4) + (g << 2) + r) * 32 + lane];
    }
    __syncthreads();
    if (wid == 2 || wid == 3) {
#pragma unroll
        for (int mt = 0; mt < 4; mt++)
#pragma unroll
            for (int g = 0; g < 4; g++)
#pragma unroll
                for (int r = 0; r < 4; r++)
                    red[wid - 2][((mt << 4) + (g << 2) + r) * 32 + lane] = acc[mt][g][r];
    }
    __syncthreads();
    if (wid < 2) {
#pragma unroll
        for (int mt = 0; mt < 4; mt++)
#pragma unroll
            for (int g = 0; g < 4; g++)
#pragma unroll
                for (int r = 0; r < 4; r++)
                    acc[mt][g][r] += red[wid][((mt << 4) + (g << 2) + r) * 32 + lane];
    }
    __syncthreads();
    if (wid == 1) {
#pragma unroll
        for (int mt = 0; mt < 4; mt++)
#pragma unroll
            for (int g = 0; g < 4; g++)
#pragma unroll
                for (int r = 0; r < 4; r++)
                    red[0][((mt << 4) + (g << 2) + r) * 32 + lane] = acc[mt][g][r];
    }
    __syncthreads();
    if (wid == 0) {
#pragma unroll
        for (int mt = 0; mt < 4; mt++)
#pragma unroll
            for (int g = 0; g < 4; g++)
#pragma unroll
                for (int r = 0; r < 4; r++) {
                    float v = acc[mt][g][r] + red[0][((mt << 4) + (g << 2) + r) * 32 + lane];
                    int b  = (mt << 4) + gid + ((r >> 1) << 3);
                    int dd = (tig << 1) + (r & 1);
                    red[2][b * 33 + (g << 3) + dd] = v;
                }
    }
    __syncthreads();

#pragma unroll
    for (int j = 0; j < 2; j++) {
        int pid = tid + (j << 8);
        int b = pid >> 3, dd = pid & 7;
        int d = d0 + dd;
        float ig = red[2][b * 33 + 0 * 8 + dd] + xg_t[(size_t)b * D4_ + 0 * D_ + d];
        float fg = red[2][b * 33 + 1 * 8 + dd] + xg_t[(size_t)b * D4_ + 1 * D_ + d];
        float gg = red[2][b * 33 + 2 * 8 + dd] + xg_t[(size_t)b * D4_ + 2 * D_ + d];
        float og = red[2][b * 33 + 3 * 8 + dd] + xg_t[(size_t)b * D4_ + 3 * D_ + d];
        size_t idx = (size_t)b * D_ + d;
        float ci = c[idx];
        float i_ = 1.f / (1.f + __expf(-ig));
        float f_ = 1.f / (1.f + __expf(-fg));
        float o_ = 1.f / (1.f + __expf(-og));
        float cn = f_ * ci + i_ * tanhf(gg);
        float hn = o_ * tanhf(cn);
        c[idx] = cn;
        hout[idx] = hn;
        float hh = __bfloat162float(__float2bfloat16(hn));
        hN_hi[idx] = __float2bfloat16(hh);
        hN_lo[idx] = __float2bfloat16(hn - hh);
    }
}

// ---------------- attention: scores/softmax/weighted -> bf16 cat ------------
__global__ __launch_bounds__(256)
void attn_kernel(const float* __restrict__ q,
                 const float* __restrict__ ctx,
                 const float* __restrict__ x,
                 __nv_bfloat16* __restrict__ cath,
                 __nv_bfloat16* __restrict__ catl,
                 float* __restrict__ attn_out)
{
    const int b = blockIdx.x;
    const int t = blockIdx.y;
    const int tb = t * B_ + b;
    __shared__ float qs[D_];
    __shared__ float sc[S_];

    const int tid = threadIdx.x;
    const int warp = tid >> 5, lane = tid & 31;

    ((float4*)qs)[tid] = ((const float4*)(q + (size_t)tb * D_))[tid];
    __syncthreads();

#pragma unroll
    for (int si = 0; si < 8; si++) {
        int s = warp * 8 + si;
        const float4* crow = (const float4*)(ctx + (size_t)(s * B_ + b) * D_);
        float sum = 0.f;
#pragma unroll
        for (int i = 0; i < 8; i++) {
            float4 cv = crow[lane + 32 * i];
            float4 qv = ((const float4*)qs)[lane + 32 * i];
            sum = fmaf(cv.x, qv.x, sum);
            sum = fmaf(cv.y, qv.y, sum);
            sum = fmaf(cv.z, qv.z, sum);
            sum = fmaf(cv.w, qv.w, sum);
        }
#pragma unroll
        for (int off = 16; off; off >>= 1)
            sum += __shfl_down_sync(0xffffffffu, sum, off);
        if (lane == 0) sc[s] = sum;
    }
    __syncthreads();

    if (warp == 0) {
        float v0 = sc[lane], v1 = sc[lane + 32];
        float m = fmaxf(v0, v1);
#pragma unroll
        for (int off = 16; off; off >>= 1)
            m = fmaxf(m, __shfl_xor_sync(0xffffffffu, m, off));
        float e0 = __expf(v0 - m), e1 = __expf(v1 - m);
        float ssum = e0 + e1;
#pragma unroll
        for (int off = 16; off; off >>= 1)
            ssum += __shfl_xor_sync(0xffffffffu, ssum, off);
        float inv = 1.f / ssum;
        sc[lane] = e0 * inv;
        sc[lane + 32] = e1 * inv;
    }
    __syncthreads();

    float4 accv = make_float4(0.f, 0.f, 0.f, 0.f);
    for (int s = 0; s < S_; s++) {
        float a = sc[s];
        float4 cv = ((const float4*)(ctx + (size_t)(s * B_ + b) * D_))[tid];
        accv.x = fmaf(a, cv.x, accv.x);
        accv.y = fmaf(a, cv.y, accv.y);
        accv.z = fmaf(a, cv.z, accv.z);
        accv.w = fmaf(a, cv.w, accv.w);
    }
    // cat = [weighted | x] as bf16 hi/lo
    __nv_bfloat162* ch = (__nv_bfloat162*)(cath + (size_t)tb * 2 * D_);
    __nv_bfloat162* cl = (__nv_bfloat162*)(catl + (size_t)tb * 2 * D_);
    split_store4(accv, ch + tid * 2, cl + tid * 2);
    float4 xv = ((const float4*)(x + (size_t)tb * D_))[tid];
    split_store4(xv, ch + D_ / 2 + tid * 2, cl + D_ / 2 + tid * 2);

    if (t == T_ - 1 && tid < S_) attn_out[b * S_ + tid] = sc[tid];
}

// ---------------- launch ----------------
extern "C" void kernel_launch(void* const* d_in, const int* in_sizes, int n_in,
                              void* d_out, int out_size)
{
    (void)in_sizes; (void)n_in; (void)out_size;

    const int*   input = (const int*)  d_in[0];
    const float* h0    = (const float*)d_in[1];
    const float* c0    = (const float*)d_in[2];
    const float* ctx   = (const float*)d_in[3];
    const float* emb   = (const float*)d_in[5];
    const float* wih0  = (const float*)d_in[6];
    const float* whh0  = (const float*)d_in[7];
    const float* bih0  = (const float*)d_in[8];
    const float* bhh0  = (const float*)d_in[9];
    const float* wih1  = (const float*)d_in[10];
    const float* whh1  = (const float*)d_in[11];
    const float* bih1  = (const float*)d_in[12];
    const float* bhh1  = (const float*)d_in[13];
    const float* w_in  = (const float*)d_in[14];
    const float* w_out = (const float*)d_in[15];

    float* out      = (float*)d_out;
    float* out_hn   = out + (size_t)TB_ * D_;
    float* out_cn   = out_hn + (size_t)2 * B_ * D_;
    float* out_attn = out_cn + (size_t)2 * B_ * D_;

    float *xg, *x1, *x2, *c, *q;
    cudaGetSymbolAddress((void**)&xg, g_xg);
    cudaGetSymbolAddress((void**)&x1, g_x1);
    cudaGetSymbolAddress((void**)&x2, g_x2);
    cudaGetSymbolAddress((void**)&c,  g_c);
    cudaGetSymbolAddress((void**)&q,  g_q);

    __nv_bfloat16 *x0h, *x0l, *sh, *sl, *h0h, *h0l, *cath, *catl;
    __nv_bfloat16 *whhh0, *whhl0, *whhh1, *whhl1;
    __nv_bfloat16 *wihh0, *wihl0, *wihh1, *wihl1, *winh, *winl, *wouth, *woutl;
    cudaGetSymbolAddress((void**)&x0h, g_x0h);   cudaGetSymbolAddress((void**)&x0l, g_x0l);
    cudaGetSymbolAddress((void**)&sh,  g_sh);    cudaGetSymbolAddress((void**)&sl,  g_sl);
    cudaGetSymbolAddress((void**)&h0h, g_h0h);   cudaGetSymbolAddress((void**)&h0l, g_h0l);
    cudaGetSymbolAddress((void**)&cath, g_cath); cudaGetSymbolAddress((void**)&catl, g_catl);
    cudaGetSymbolAddress((void**)&whhh0, g_whhh0); cudaGetSymbolAddress((void**)&whhl0, g_whhl0);
    cudaGetSymbolAddress((void**)&whhh1, g_whhh1); cudaGetSymbolAddress((void**)&whhl1, g_whhl1);
    cudaGetSymbolAddress((void**)&wihh0, g_wihh0); cudaGetSymbolAddress((void**)&wihl0, g_wihl0);
    cudaGetSymbolAddress((void**)&wihh1, g_wihh1); cudaGetSymbolAddress((void**)&wihl1, g_wihl1);
    cudaGetSymbolAddress((void**)&winh,  g_winh);  cudaGetSymbolAddress((void**)&winl,  g_winl);
    cudaGetSymbolAddress((void**)&wouth, g_wouth); cudaGetSymbolAddress((void**)&woutl, g_woutl);

    const size_t BD = (size_t)B_ * D_;

    // 0) weight splits
    split_kernel<<<4096, 256>>>(whh0, whhh0, whhl0, D4_ * D_ / 4);
    split_kernel<<<4096, 256>>>(whh1, whhh1, whhl1, D4_ * D_ / 4);
    split_kernel<<<4096, 256>>>(wih0, wihh0, wihl0, D4_ * D_ / 4);
    split_kernel<<<4096, 256>>>(wih1, wihh1, wihl1, D4_ * D_ / 4);
    split_kernel<<<1024, 256>>>(w_in, winh, winl, D_ * D_ / 4);
    split_kernel<<<2048, 256>>>(w_out, wouth, woutl, D_ * 2 * D_ / 4);

    // 1) embedding -> bf16 hi/lo
    embed_kernel<<<TB_, 256>>>(input, emb, x0h, x0l);

    // 2) layer 0: input-gate GEMM + 32 steps
    hgemm_nt<1><<<dim3(D4_ / 128, TB_ / 128), 256>>>(
        x0h, x0l, wihh0, wihl0, xg, TB_, D4_, D_, bih0, bhh0);
    split_kernel<<<64, 256>>>(h0, h0h, h0l, (int)(BD / 4));
    cudaMemcpyAsync(c, c0, BD * sizeof(float), cudaMemcpyDeviceToDevice, 0);
    for (int t = 0; t < T_; t++) {
        const __nv_bfloat16* ah = (t == 0) ? h0h : sh + (size_t)(t - 1) * BD;
        const __nv_bfloat16* al = (t == 0) ? h0l : sl + (size_t)(t - 1) * BD;
        lstm_step_mma<<<128, 256>>>(ah, al, whhh0, whhl0,
                                    xg + (size_t)t * B_ * D4_, c,
                                    x1 + (size_t)t * BD,
                                    sh + (size_t)t * BD, sl + (size_t)t * BD);
    }
    cudaMemcpyAsync(out_hn, x1 + (size_t)(T_ - 1) * BD, BD * sizeof(float),
                    cudaMemcpyDeviceToDevice, 0);
    cudaMemcpyAsync(out_cn, c, BD * sizeof(float), cudaMemcpyDeviceToDevice, 0);

    // 3) layer 1: input-gate GEMM (A = layer0 h sequence, bf16) + 32 steps
    hgemm_nt<1><<<dim3(D4_ / 128, TB_ / 128), 256>>>(
        sh, sl, wihh1, wihl1, xg, TB_, D4_, D_, bih1, bhh1);
    split_kernel<<<64, 256>>>(h0 + BD, h0h, h0l, (int)(BD / 4));
    cudaMemcpyAsync(c, c0 + BD, BD * sizeof(float), cudaMemcpyDeviceToDevice, 0);
    for (int t = 0; t < T_; t++) {
        const __nv_bfloat16* ah = (t == 0) ? h0h : sh + (size_t)(t - 1) * BD;
        const __nv_bfloat16* al = (t == 0) ? h0l : sl + (size_t)(t - 1) * BD;
        lstm_step_mma<<<128, 256>>>(ah, al, whhh1, whhl1,
                                    xg + (size_t)t * B_ * D4_, c,
                                    x2 + (size_t)t * BD,
                                    sh + (size_t)t * BD, sl + (size_t)t * BD);
    }
    cudaMemcpyAsync(out_hn + BD, x2 + (size_t)(T_ - 1) * BD, BD * sizeof(float),
                    cudaMemcpyDeviceToDevice, 0);
    cudaMemcpyAsync(out_cn + BD, c, BD * sizeof(float), cudaMemcpyDeviceToDevice, 0);

    // 4) attention: q = x2 @ w_in^T (bf16), then fused attn -> bf16 cat
    hgemm_nt<0><<<dim3(D_ / 128, TB_ / 128), 256>>>(
        sh, sl, winh, winl, q, TB_, D_, D_, nullptr, nullptr);
    attn_kernel<<<dim3(B_, T_), 256>>>(q, ctx, x2, cath, catl, out_attn);

    // 5) out = tanh(cat @ w_out^T)
    hgemm_nt<2><<<dim3(D_ / 128, TB_ / 128), 256>>>(
        cath, catl, wouth, woutl, out, TB_, D_, 2 * D_, nullptr, nullptr);
}

// round 6
// speedup vs baseline: 1.4049x; 1.4049x over previous
#include <cuda_runtime.h>
#include <cuda_bf16.h>
#include <math.h>

#define T_ 32
#define B_ 64
#define S_ 64
#define D_ 1024
#define D4_ 4096
#define TB_ 2048

// ---------------- scratch (device globals) ----------------
__device__ float g_xg[TB_ * D4_];
__device__ float g_x1[TB_ * D_];
__device__ float g_x2[TB_ * D_];
__device__ float g_c [B_ * D_];
__device__ float g_q [TB_ * D_];

__device__ __align__(16) __nv_bfloat16 g_x0h[TB_ * D_], g_x0l[TB_ * D_];
__device__ __align__(16) __nv_bfloat16 g_sh [TB_ * D_], g_sl [TB_ * D_];
__device__ __align__(16) __nv_bfloat16 g_h0h[B_ * D_],  g_h0l[B_ * D_];
__device__ __align__(16) __nv_bfloat16 g_cath[TB_ * 2 * D_], g_catl[TB_ * 2 * D_];

__device__ __align__(16) __nv_bfloat16 g_whhh0[D4_ * D_], g_whhl0[D4_ * D_];
__device__ __align__(16) __nv_bfloat16 g_whhh1[D4_ * D_], g_whhl1[D4_ * D_];
__device__ __align__(16) __nv_bfloat16 g_wihh0[D4_ * D_], g_wihl0[D4_ * D_];
__device__ __align__(16) __nv_bfloat16 g_wihh1[D4_ * D_], g_wihl1[D4_ * D_];
__device__ __align__(16) __nv_bfloat16 g_winh[D_ * D_],   g_winl[D_ * D_];
__device__ __align__(16) __nv_bfloat16 g_wouth[D_ * 2 * D_], g_woutl[D_ * 2 * D_];

// ---------------- helpers ----------------
__device__ __forceinline__ void mma16816(float* d, const unsigned* a, const unsigned* b)
{
    asm volatile(
        "mma.sync.aligned.m16n8k16.row.col.f32.bf16.bf16.f32 "
        "{%0,%1,%2,%3}, {%4,%5,%6,%7}, {%8,%9}, {%0,%1,%2,%3};"
        : "+f"(d[0]), "+f"(d[1]), "+f"(d[2]), "+f"(d[3])
        : "r"(a[0]), "r"(a[1]), "r"(a[2]), "r"(a[3]),
          "r"(b[0]), "r"(b[1]));
}
__device__ __forceinline__ void ldsm_x4(unsigned* r, unsigned addr)
{
    asm volatile("ldmatrix.sync.aligned.m8n8.x4.shared.b16 {%0,%1,%2,%3}, [%4];"
                 : "=r"(r[0]), "=r"(r[1]), "=r"(r[2]), "=r"(r[3]) : "r"(addr));
}
__device__ __forceinline__ void ldsm_x2(unsigned* r, unsigned addr)
{
    asm volatile("ldmatrix.sync.aligned.m8n8.x2.shared.b16 {%0,%1}, [%2];"
                 : "=r"(r[0]), "=r"(r[1]) : "r"(addr));
}
__device__ __forceinline__ void cpa16(unsigned saddr, const void* g)
{
    asm volatile("cp.async.cg.shared.global [%0], [%1], 16;" :: "r"(saddr), "l"(g) : "memory");
}
__device__ __forceinline__ void cp_commit() { asm volatile("cp.async.commit_group;" ::: "memory"); }
__device__ __forceinline__ void cp_wait1()  { asm volatile("cp.async.wait_group 1;" ::: "memory"); }
__device__ __forceinline__ void cp_wait0()  { asm volatile("cp.async.wait_group 0;" ::: "memory"); }

__device__ __forceinline__ void split_store4(float4 v,
                                             __nv_bfloat162* hp,
                                             __nv_bfloat162* lp)
{
    float hx = __bfloat162float(__float2bfloat16(v.x));
    float hy = __bfloat162float(__float2bfloat16(v.y));
    float hz = __bfloat162float(__float2bfloat16(v.z));
    float hw = __bfloat162float(__float2bfloat16(v.w));
    hp[0] = __nv_bfloat162(__float2bfloat16(hx), __float2bfloat16(hy));
    hp[1] = __nv_bfloat162(__float2bfloat16(hz), __float2bfloat16(hw));
    lp[0] = __nv_bfloat162(__float2bfloat16(v.x - hx), __float2bfloat16(v.y - hy));
    lp[1] = __nv_bfloat162(__float2bfloat16(v.z - hz), __float2bfloat16(v.w - hw));
}

__global__ void split_kernel(const float* __restrict__ w,
                             __nv_bfloat16* __restrict__ hi,
                             __nv_bfloat16* __restrict__ lo, int n4)
{
    int i = blockIdx.x * blockDim.x + threadIdx.x;
    if (i >= n4) return;
    float4 v = ((const float4*)w)[i];
    split_store4(v, (__nv_bfloat162*)hi + i * 2, (__nv_bfloat162*)lo + i * 2);
}

__global__ void embed_kernel(const int* __restrict__ tok,
                             const float* __restrict__ emb,
                             __nv_bfloat16* __restrict__ xh,
                             __nv_bfloat16* __restrict__ xl)
{
    int tb = blockIdx.x;
    int t4 = threadIdx.x;
    int tk = tok[tb];
    float4 v = make_float4(0.f, 0.f, 0.f, 0.f);
    if (tk != 0) v = ((const float4*)(emb + (size_t)tk * D_))[t4];
    split_store4(v, (__nv_bfloat162*)(xh + (size_t)tb * D_) + t4 * 2,
                    (__nv_bfloat162*)(xl + (size_t)tb * D_) + t4 * 2);
}

// ---------------- bf16 tensor GEMM, smem-staged + cp.async + ldmatrix -------
// C = A @ B^T (3-term compensated). A,B row-major (rows x K) bf16 hi/lo.
// Block 128x128, BK=32, double-buffered; 8 warps (2x4), warp tile 64x32.
// EPI: 0 none, 1 +bias1[n]+bias2[n], 2 tanh
template<int EPI>
__global__ __launch_bounds__(256)
void hgemm_nt(const __nv_bfloat16* __restrict__ Ahi,
              const __nv_bfloat16* __restrict__ Alo,
              const __nv_bfloat16* __restrict__ Bhi,
              const __nv_bfloat16* __restrict__ Blo,
              float* __restrict__ C, int M, int N, int K,
              const float* __restrict__ bias1, const float* __restrict__ bias2)
{
    __shared__ __nv_bfloat16 As[2][2][128][16];   // [buf][kh][row][col16]
    __shared__ __nv_bfloat16 Bs[2][2][128][16];

    const int tid  = threadIdx.x;
    const int wid  = tid >> 5;
    const int lane = tid & 31;
    const int gid  = lane >> 2;
    const int tig  = lane & 3;
    const int wm   = wid >> 2;       // 0..1
    const int wn   = wid & 3;        // 0..3
    const int bm   = blockIdx.y * 128;
    const int bn   = blockIdx.x * 128;
    const int KC   = K >> 5;         // 32-wide chunks per pass
    const int total = 3 * KC;

    float acc[4][4][4];
#pragma unroll
    for (int mt = 0; mt < 4; mt++)
#pragma unroll
        for (int nt = 0; nt < 4; nt++)
#pragma unroll
            for (int r = 0; r < 4; r++) acc[mt][nt][r] = 0.f;

    // per-thread staging coords: each thread does 2 x 16B per matrix per chunk
    const int srow = tid >> 1;           // 0..127
    const int shalf = tid & 1;           // 16B half within a 32B k16-row

    auto issue = [&](int it) {
        int p  = it / KC;
        int kc = (it - p * KC) << 5;     // k base (bf16 units)
        const __nv_bfloat16* Asrc = (p == 1) ? Alo : Ahi;
        const __nv_bfloat16* Bsrc = (p == 2) ? Blo : Bhi;
        int buf = it & 1;
#pragma unroll
        for (int kh = 0; kh < 2; kh++) {
            const __nv_bfloat16* ga =
                Asrc + (size_t)(bm + srow) * K + kc + kh * 16 + shalf * 8;
            cpa16((unsigned)__cvta_generic_to_shared(&As[buf][kh][srow][shalf * 8]), ga);
            const __nv_bfloat16* gb =
                Bsrc + (size_t)(bn + srow) * K + kc + kh * 16 + shalf * 8;
            cpa16((unsigned)__cvta_generic_to_shared(&Bs[buf][kh][srow][shalf * 8]), gb);
        }
        cp_commit();
    };

    // fragment smem addresses (constant per thread, per buf/kh recomputed)
    const int arow = (wm << 6) + (lane & 15);    // + mt*16
    const int acol = (lane >> 4) << 3;
    const int brow = (wn << 5) + (lane & 7);     // + nt*8
    const int bcol = ((lane >> 3) & 1) << 3;

    issue(0);
    for (int it = 0; it < total; it++) {
        if (it + 1 < total) { issue(it + 1); cp_wait1(); }
        else                { cp_wait0(); }
        __syncthreads();
        const int buf = it & 1;
#pragma unroll
        for (int kh = 0; kh < 2; kh++) {
            unsigned a[4][4], b[4][2];
#pragma unroll
            for (int mt = 0; mt < 4; mt++)
                ldsm_x4(a[mt], (unsigned)__cvta_generic_to_shared(
                    &As[buf][kh][arow + (mt << 4)][acol]));
#pragma unroll
            for (int nt = 0; nt < 4; nt++)
                ldsm_x2(b[nt], (unsigned)__cvta_generic_to_shared(
                    &Bs[buf][kh][brow + (nt << 3)][bcol]));
#pragma unroll
            for (int mt = 0; mt < 4; mt++)
#pragma unroll
                for (int nt = 0; nt < 4; nt++)
                    mma16816(acc[mt][nt], a[mt], b[nt]);
        }
        __syncthreads();
    }

    // epilogue
#pragma unroll
    for (int mt = 0; mt < 4; mt++)
#pragma unroll
        for (int nt = 0; nt < 4; nt++)
#pragma unroll
            for (int rp = 0; rp < 2; rp++) {
                int row = bm + (wm << 6) + (mt << 4) + gid + (rp << 3);
                int col = bn + (wn << 5) + (nt << 3) + (tig << 1);
                float v0 = acc[mt][nt][rp * 2];
                float v1 = acc[mt][nt][rp * 2 + 1];
                if (EPI == 1) {
                    v0 += __ldg(bias1 + col) + __ldg(bias2 + col);
                    v1 += __ldg(bias1 + col + 1) + __ldg(bias2 + col + 1);
                }
                if (EPI == 2) { v0 = tanhf(v0); v1 = tanhf(v1); }
                float2 o; o.x = v0; o.y = v1;
                *(float2*)(C + (size_t)row * N + col) = o;
            }
}

// ---------------- LSTM step via bf16 mma, 3-term split (R4-proven) ----------
__global__ __launch_bounds__(256, 1)
void lstm_step_mma(const __nv_bfloat16* __restrict__ hA_hi,
                   const __nv_bfloat16* __restrict__ hA_lo,
                   const __nv_bfloat16* __restrict__ w_hi,
                   const __nv_bfloat16* __restrict__ w_lo,
                   const float* __restrict__ xg_t,
                   float* __restrict__ c,
                   float* __restrict__ hout,
                   __nv_bfloat16* __restrict__ hN_hi,
                   __nv_bfloat16* __restrict__ hN_lo)
{
    __shared__ float red[4][2112];

    const int tid  = threadIdx.x;
    const int wid  = tid >> 5;
    const int lane = tid & 31;
    const int gid  = lane >> 2;
    const int tig  = lane & 3;
    const int d0   = blockIdx.x << 3;

    float acc[4][4][4];
#pragma unroll
    for (int mt = 0; mt < 4; mt++)
#pragma unroll
        for (int g = 0; g < 4; g++)
#pragma unroll
            for (int r = 0; r < 4; r++) acc[mt][g][r] = 0.f;

    const unsigned* Hs[3] = { (const unsigned*)hA_hi, (const unsigned*)hA_lo,
                              (const unsigned*)hA_hi };
    const unsigned* Ws[3] = { (const unsigned*)w_hi, (const unsigned*)w_hi,
                              (const unsigned*)w_lo };
    const int kw = wid << 7;

#pragma unroll
    for (int p = 0; p < 3; p++) {
        const unsigned* H = Hs[p];
        const unsigned* W = Ws[p];
#pragma unroll
        for (int s = 0; s < 8; s++) {
            const int kc = (kw + s * 16 + tig * 2) >> 1;
            unsigned a[4][4], b[4][2];
#pragma unroll
            for (int mt = 0; mt < 4; mt++) {
                int r0 = ((mt << 4) + gid) << 9;
                a[mt][0] = __ldg(H + r0 + kc);
                a[mt][1] = __ldg(H + r0 + (8 << 9) + kc);
                a[mt][2] = __ldg(H + r0 + kc + 4);
                a[mt][3] = __ldg(H + r0 + (8 << 9) + kc + 4);
            }
#pragma unroll
            for (int g = 0; g < 4; g++) {
                int rn = ((g << 10) + d0 + gid) << 9;
                b[g][0] = __ldg(W + rn + kc);
                b[g][1] = __ldg(W + rn + kc + 4);
            }
#pragma unroll
            for (int mt = 0; mt < 4; mt++)
#pragma unroll
                for (int g = 0; g < 4; g++)
                    mma16816(acc[mt][g], a[mt], b[g]);
        }
    }

    if (wid >= 4) {
#pragma unroll
        for (int mt = 0; mt < 4; mt++)
#pragma unroll
            for (int g = 0; g < 4; g++)
#pragma unroll
                for (int r = 0; r < 4; r++)
                    red[wid - 4][((mt << 4) + (g << 2) + r) * 32 + lane] = acc[mt][g][r];
    }
    __syncthreads();
    if (wid < 4) {
#pragma unroll
        for (int mt = 0; mt < 4; mt++)
#pragma unroll
            for (int g = 0; g < 4; g++)
#pragma unroll
                for (int r = 0; r < 4; r++)
                    acc[mt][g][r] += red[wid][((mt << 4) + (g << 2) + r) * 32 + lane];
    }
    __syncthreads();
    if (wid == 2 || wid == 3) {
#pragma unroll
        for (int mt = 0; mt < 4; mt++)
#pragma unroll
            for (int g = 0; g < 4; g++)
#pragma unroll
                for (int r = 0; r < 4; r++)
                    red[wid - 2][((mt << 4) + (g << 2) + r) * 32 + lane] = acc[mt][g][r];
    }
    __syncthreads();
    if (wid < 2) {
#pragma unroll
        for (int mt = 0; mt < 4; mt++)
#pragma unroll
            for (int g = 0; g < 4; g++)
#pragma unroll
                for (int r = 0; r < 4; r++)
                    acc[mt][g][r] += red[wid][((mt << 4) + (g << 2) + r) * 32 + lane];
    }
    __syncthreads();
    if (wid == 1) {
#pragma unroll
        for (int mt = 0; mt < 4; mt++)
#pragma unroll
            for (int g = 0; g < 4; g++)
#pragma unroll
                for (int r = 0; r < 4; r++)
                    red[0][((mt << 4) + (g << 2) + r) * 32 + lane] = acc[mt][g][r];
    }
    __syncthreads();
    if (wid == 0) {
#pragma unroll
        for (int mt = 0; mt < 4; mt++)
#pragma unroll
            for (int g = 0; g < 4; g++)
#pragma unroll
                for (int r = 0; r < 4; r++) {
                    float v = acc[mt][g][r] + red[0][((mt << 4) + (g << 2) + r) * 32 + lane];
                    int b  = (mt << 4) + gid + ((r >> 1) << 3);
                    int dd = (tig << 1) + (r & 1);
                    red[2][b * 33 + (g << 3) + dd] = v;
                }
    }
    __syncthreads();

#pragma unroll
    for (int j = 0; j < 2; j++) {
        int pid = tid + (j << 8);
        int b = pid >> 3, dd = pid & 7;
        int d = d0 + dd;
        float ig = red[2][b * 33 + 0 * 8 + dd] + xg_t[(size_t)b * D4_ + 0 * D_ + d];
        float fg = red[2][b * 33 + 1 * 8 + dd] + xg_t[(size_t)b * D4_ + 1 * D_ + d];
        float gg = red[2][b * 33 + 2 * 8 + dd] + xg_t[(size_t)b * D4_ + 2 * D_ + d];
        float og = red[2][b * 33 + 3 * 8 + dd] + xg_t[(size_t)b * D4_ + 3 * D_ + d];
        size_t idx = (size_t)b * D_ + d;
        float ci = c[idx];
        float i_ = 1.f / (1.f + __expf(-ig));
        float f_ = 1.f / (1.f + __expf(-fg));
        float o_ = 1.f / (1.f + __expf(-og));
        float cn = f_ * ci + i_ * tanhf(gg);
        float hn = o_ * tanhf(cn);
        c[idx] = cn;
        hout[idx] = hn;
        float hh = __bfloat162float(__float2bfloat16(hn));
        hN_hi[idx] = __float2bfloat16(hh);
        hN_lo[idx] = __float2bfloat16(hn - hh);
    }
}

// ---------------- attention ----------------
__global__ __launch_bounds__(256)
void attn_kernel(const float* __restrict__ q,
                 const float* __restrict__ ctx,
                 const float* __restrict__ x,
                 __nv_bfloat16* __restrict__ cath,
                 __nv_bfloat16* __restrict__ catl,
                 float* __restrict__ attn_out)
{
    const int b = blockIdx.x;
    const int t = blockIdx.y;
    const int tb = t * B_ + b;
    __shared__ float qs[D_];
    __shared__ float sc[S_];

    const int tid = threadIdx.x;
    const int warp = tid >> 5, lane = tid & 31;

    ((float4*)qs)[tid] = ((const float4*)(q + (size_t)tb * D_))[tid];
    __syncthreads();

#pragma unroll
    for (int si = 0; si < 8; si++) {
        int s = warp * 8 + si;
        const float4* crow = (const float4*)(ctx + (size_t)(s * B_ + b) * D_);
        float sum = 0.f;
#pragma unroll
        for (int i = 0; i < 8; i++) {
            float4 cv = crow[lane + 32 * i];
            float4 qv = ((const float4*)qs)[lane + 32 * i];
            sum = fmaf(cv.x, qv.x, sum);
            sum = fmaf(cv.y, qv.y, sum);
            sum = fmaf(cv.z, qv.z, sum);
            sum = fmaf(cv.w, qv.w, sum);
        }
#pragma unroll
        for (int off = 16; off; off >>= 1)
            sum += __shfl_down_sync(0xffffffffu, sum, off);
        if (lane == 0) sc[s] = sum;
    }
    __syncthreads();

    if (warp == 0) {
        float v0 = sc[lane], v1 = sc[lane + 32];
        float m = fmaxf(v0, v1);
#pragma unroll
        for (int off = 16; off; off >>= 1)
            m = fmaxf(m, __shfl_xor_sync(0xffffffffu, m, off));
        float e0 = __expf(v0 - m), e1 = __expf(v1 - m);
        float ssum = e0 + e1;
#pragma unroll
        for (int off = 16; off; off >>= 1)
            ssum += __shfl_xor_sync(0xffffffffu, ssum, off);
        float inv = 1.f / ssum;
        sc[lane] = e0 * inv;
        sc[lane + 32] = e1 * inv;
    }
    __syncthreads();

    float4 accv = make_float4(0.f, 0.f, 0.f, 0.f);
    for (int s = 0; s < S_; s++) {
        float a = sc[s];
        float4 cv = ((const float4*)(ctx + (size_t)(s * B_ + b) * D_))[tid];
        accv.x = fmaf(a, cv.x, accv.x);
        accv.y = fmaf(a, cv.y, accv.y);
        accv.z = fmaf(a, cv.z, accv.z);
        accv.w = fmaf(a, cv.w, accv.w);
    }
    __nv_bfloat162* ch = (__nv_bfloat162*)(cath + (size_t)tb * 2 * D_);
    __nv_bfloat162* cl = (__nv_bfloat162*)(catl + (size_t)tb * 2 * D_);
    split_store4(accv, ch + tid * 2, cl + tid * 2);
    float4 xv = ((const float4*)(x + (size_t)tb * D_))[tid];
    split_store4(xv, ch + D_ / 2 + tid * 2, cl + D_ / 2 + tid * 2);

    if (t == T_ - 1 && tid < S_) attn_out[b * S_ + tid] = sc[tid];
}

// ---------------- launch ----------------
extern "C" void kernel_launch(void* const* d_in, const int* in_sizes, int n_in,
                              void* d_out, int out_size)
{
    (void)in_sizes; (void)n_in; (void)out_size;

    const int*   input = (const int*)  d_in[0];
    const float* h0    = (const float*)d_in[1];
    const float* c0    = (const float*)d_in[2];
    const float* ctx   = (const float*)d_in[3];
    const float* emb   = (const float*)d_in[5];
    const float* wih0  = (const float*)d_in[6];
    const float* whh0  = (const float*)d_in[7];
    const float* bih0  = (const float*)d_in[8];
    const float* bhh0  = (const float*)d_in[9];
    const float* wih1  = (const float*)d_in[10];
    const float* whh1  = (const float*)d_in[11];
    const float* bih1  = (const float*)d_in[12];
    const float* bhh1  = (const float*)d_in[13];
    const float* w_in  = (const float*)d_in[14];
    const float* w_out = (const float*)d_in[15];

    float* out      = (float*)d_out;
    float* out_hn   = out + (size_t)TB_ * D_;
    float* out_cn   = out_hn + (size_t)2 * B_ * D_;
    float* out_attn = out_cn + (size_t)2 * B_ * D_;

    float *xg, *x1, *x2, *c, *q;
    cudaGetSymbolAddress((void**)&xg, g_xg);
    cudaGetSymbolAddress((void**)&x1, g_x1);
    cudaGetSymbolAddress((void**)&x2, g_x2);
    cudaGetSymbolAddress((void**)&c,  g_c);
    cudaGetSymbolAddress((void**)&q,  g_q);

    __nv_bfloat16 *x0h, *x0l, *sh, *sl, *h0h, *h0l, *cath, *catl;
    __nv_bfloat16 *whhh0, *whhl0, *whhh1, *whhl1;
    __nv_bfloat16 *wihh0, *wihl0, *wihh1, *wihl1, *winh, *winl, *wouth, *woutl;
    cudaGetSymbolAddress((void**)&x0h, g_x0h);   cudaGetSymbolAddress((void**)&x0l, g_x0l);
    cudaGetSymbolAddress((void**)&sh,  g_sh);    cudaGetSymbolAddress((void**)&sl,  g_sl);
    cudaGetSymbolAddress((void**)&h0h, g_h0h);   cudaGetSymbolAddress((void**)&h0l, g_h0l);
    cudaGetSymbolAddress((void**)&cath, g_cath); cudaGetSymbolAddress((void**)&catl, g_catl);
    cudaGetSymbolAddress((void**)&whhh0, g_whhh0); cudaGetSymbolAddress((void**)&whhl0, g_whhl0);
    cudaGetSymbolAddress((void**)&whhh1, g_whhh1); cudaGetSymbolAddress((void**)&whhl1, g_whhl1);
    cudaGetSymbolAddress((void**)&wihh0, g_wihh0); cudaGetSymbolAddress((void**)&wihl0, g_wihl0);
    cudaGetSymbolAddress((void**)&wihh1, g_wihh1); cudaGetSymbolAddress((void**)&wihl1, g_wihl1);
    cudaGetSymbolAddress((void**)&winh,  g_winh);  cudaGetSymbolAddress((void**)&winl,  g_winl);
    cudaGetSymbolAddress((void**)&wouth, g_wouth); cudaGetSymbolAddress((void**)&woutl, g_woutl);

    const size_t BD = (size_t)B_ * D_;

    // 0) weight splits
    split_kernel<<<4096, 256>>>(whh0, whhh0, whhl0, D4_ * D_ / 4);
    split_kernel<<<4096, 256>>>(whh1, whhh1, whhl1, D4_ * D_ / 4);
    split_kernel<<<4096, 256>>>(wih0, wihh0, wihl0, D4_ * D_ / 4);
    split_kernel<<<4096, 256>>>(wih1, wihh1, wihl1, D4_ * D_ / 4);
    split_kernel<<<1024, 256>>>(w_in, winh, winl, D_ * D_ / 4);
    split_kernel<<<2048, 256>>>(w_out, wouth, woutl, D_ * 2 * D_ / 4);

    // 1) embedding -> bf16 hi/lo
    embed_kernel<<<TB_, 256>>>(input, emb, x0h, x0l);

    // 2) layer 0
    hgemm_nt<1><<<dim3(D4_ / 128, TB_ / 128), 256>>>(
        x0h, x0l, wihh0, wihl0, xg, TB_, D4_, D_, bih0, bhh0);
    split_kernel<<<64, 256>>>(h0, h0h, h0l, (int)(BD / 4));
    cudaMemcpyAsync(c, c0, BD * sizeof(float), cudaMemcpyDeviceToDevice, 0);
    for (int t = 0; t < T_; t++) {
        const __nv_bfloat16* ah = (t == 0) ? h0h : sh + (size_t)(t - 1) * BD;
        const __nv_bfloat16* al = (t == 0) ? h0l : sl + (size_t)(t - 1) * BD;
        lstm_step_mma<<<128, 256>>>(ah, al, whhh0, whhl0,
                                    xg + (size_t)t * B_ * D4_, c,
                                    x1 + (size_t)t * BD,
                                    sh + (size_t)t * BD, sl + (size_t)t * BD);
    }
    cudaMemcpyAsync(out_hn, x1 + (size_t)(T_ - 1) * BD, BD * sizeof(float),
                    cudaMemcpyDeviceToDevice, 0);
    cudaMemcpyAsync(out_cn, c, BD * sizeof(float), cudaMemcpyDeviceToDevice, 0);

    // 3) layer 1
    hgemm_nt<1><<<dim3(D4_ / 128, TB_ / 128), 256>>>(
        sh, sl, wihh1, wihl1, xg, TB_, D4_, D_, bih1, bhh1);
    split_kernel<<<64, 256>>>(h0 + BD, h0h, h0l, (int)(BD / 4));
    cudaMemcpyAsync(c, c0 + BD, BD * sizeof(float), cudaMemcpyDeviceToDevice, 0);
    for (int t = 0; t < T_; t++) {
        const __nv_bfloat16* ah = (t == 0) ? h0h : sh + (size_t)(t - 1) * BD;
        const __nv_bfloat16* al = (t == 0) ? h0l : sl + (size_t)(t - 1) * BD;
        lstm_step_mma<<<128, 256>>>(ah, al, whhh1, whhl1,
                                    xg + (size_t)t * B_ * D4_, c,
                                    x2 + (size_t)t * BD,
                                    sh + (size_t)t * BD, sl + (size_t)t * BD);
    }
    cudaMemcpyAsync(out_hn + BD, x2 + (size_t)(T_ - 1) * BD, BD * sizeof(float),
                    cudaMemcpyDeviceToDevice, 0);
    cudaMemcpyAsync(out_cn + BD, c, BD * sizeof(float), cudaMemcpyDeviceToDevice, 0);

    // 4) attention
    hgemm_nt<0><<<dim3(D_ / 128, TB_ / 128), 256>>>(
        sh, sl, winh, winl, q, TB_, D_, D_, nullptr, nullptr);
    attn_kernel<<<dim3(B_, T_), 256>>>(q, ctx, x2, cath, catl, out_attn);

    // 5) out = tanh(cat @ w_out^T)
    hgemm_nt<2><<<dim3(D_ / 128, TB_ / 128), 256>>>(
        cath, catl, wouth, woutl, out, TB_, D_, 2 * D_, nullptr, nullptr);
}

// round 7
// speedup vs baseline: 1.5848x; 1.1281x over previous
#include <cuda_runtime.h>
#include <cuda_bf16.h>
#include <math.h>

#define T_ 32
#define B_ 64
#define S_ 64
#define D_ 1024
#define D4_ 4096
#define TB_ 2048
#define BD_ (B_ * D_)

// ---------------- scratch (device globals) ----------------
__device__ float g_xg[TB_ * D4_];
__device__ float g_x1[TB_ * D_];
__device__ float g_x2[TB_ * D_];
__device__ float g_q [TB_ * D_];

__device__ __align__(16) __nv_bfloat16 g_x0h[TB_ * D_], g_x0l[TB_ * D_];
__device__ __align__(16) __nv_bfloat16 g_sh [TB_ * D_], g_sl [TB_ * D_];
__device__ __align__(16) __nv_bfloat16 g_h0h[BD_],      g_h0l[BD_];
__device__ __align__(16) __nv_bfloat16 g_cath[TB_ * 2 * D_], g_catl[TB_ * 2 * D_];

__device__ __align__(16) __nv_bfloat16 g_whhh0[D4_ * D_], g_whhl0[D4_ * D_];
__device__ __align__(16) __nv_bfloat16 g_whhh1[D4_ * D_], g_whhl1[D4_ * D_];
__device__ __align__(16) __nv_bfloat16 g_wihh0[D4_ * D_], g_wihl0[D4_ * D_];
__device__ __align__(16) __nv_bfloat16 g_wihh1[D4_ * D_], g_wihl1[D4_ * D_];
__device__ __align__(16) __nv_bfloat16 g_winh[D_ * D_],   g_winl[D_ * D_];
__device__ __align__(16) __nv_bfloat16 g_wouth[D_ * 2 * D_], g_woutl[D_ * 2 * D_];

// grid-barrier state (reset at end of each persistent launch)
__device__ unsigned g_cnt;
__device__ unsigned g_done;

// ---------------- asm helpers ----------------
__device__ __forceinline__ void mma16816(float* d, const unsigned* a, const unsigned* b)
{
    asm volatile(
        "mma.sync.aligned.m16n8k16.row.col.f32.bf16.bf16.f32 "
        "{%0,%1,%2,%3}, {%4,%5,%6,%7}, {%8,%9}, {%0,%1,%2,%3};"
        : "+f"(d[0]), "+f"(d[1]), "+f"(d[2]), "+f"(d[3])
        : "r"(a[0]), "r"(a[1]), "r"(a[2]), "r"(a[3]),
          "r"(b[0]), "r"(b[1]));
}
__device__ __forceinline__ void ldsm_x4(unsigned* r, unsigned addr)
{
    asm volatile("ldmatrix.sync.aligned.m8n8.x4.shared.b16 {%0,%1,%2,%3}, [%4];"
                 : "=r"(r[0]), "=r"(r[1]), "=r"(r[2]), "=r"(r[3]) : "r"(addr));
}
__device__ __forceinline__ void ldsm_x2(unsigned* r, unsigned addr)
{
    asm volatile("ldmatrix.sync.aligned.m8n8.x2.shared.b16 {%0,%1}, [%2];"
                 : "=r"(r[0]), "=r"(r[1]) : "r"(addr));
}
__device__ __forceinline__ void cpa16(unsigned saddr, const void* g)
{
    asm volatile("cp.async.cg.shared.global [%0], [%1], 16;" :: "r"(saddr), "l"(g) : "memory");
}
__device__ __forceinline__ void cp_commit() { asm volatile("cp.async.commit_group;" ::: "memory"); }
__device__ __forceinline__ void cp_wait1()  { asm volatile("cp.async.wait_group 1;" ::: "memory"); }
__device__ __forceinline__ void cp_wait0()  { asm volatile("cp.async.wait_group 0;" ::: "memory"); }

__device__ __forceinline__ void split_store4(float4 v,
                                             __nv_bfloat162* hp,
                                             __nv_bfloat162* lp)
{
    float hx = __bfloat162float(__float2bfloat16(v.x));
    float hy = __bfloat162float(__float2bfloat16(v.y));
    float hz = __bfloat162float(__float2bfloat16(v.z));
    float hw = __bfloat162float(__float2bfloat16(v.w));
    hp[0] = __nv_bfloat162(__float2bfloat16(hx), __float2bfloat16(hy));
    hp[1] = __nv_bfloat162(__float2bfloat16(hz), __float2bfloat16(hw));
    lp[0] = __nv_bfloat162(__float2bfloat16(v.x - hx), __float2bfloat16(v.y - hy));
    lp[1] = __nv_bfloat162(__float2bfloat16(v.z - hz), __float2bfloat16(v.w - hw));
}

__global__ void split_kernel(const float* __restrict__ w,
                             __nv_bfloat16* __restrict__ hi,
                             __nv_bfloat16* __restrict__ lo, int n4)
{
    int i = blockIdx.x * blockDim.x + threadIdx.x;
    if (i >= n4) return;
    float4 v = ((const float4*)w)[i];
    split_store4(v, (__nv_bfloat162*)hi + i * 2, (__nv_bfloat162*)lo + i * 2);
}

__global__ void embed_kernel(const int* __restrict__ tok,
                             const float* __restrict__ emb,
                             __nv_bfloat16* __restrict__ xh,
                             __nv_bfloat16* __restrict__ xl)
{
    int tb = blockIdx.x;
    int t4 = threadIdx.x;
    int tk = tok[tb];
    float4 v = make_float4(0.f, 0.f, 0.f, 0.f);
    if (tk != 0) v = ((const float4*)(emb + (size_t)tk * D_))[t4];
    split_store4(v, (__nv_bfloat162*)(xh + (size_t)tb * D_) + t4 * 2,
                    (__nv_bfloat162*)(xl + (size_t)tb * D_) + t4 * 2);
}

// ---------------- bf16 tensor GEMM (R6-proven) ----------------
template<int EPI>
__global__ __launch_bounds__(256)
void hgemm_nt(const __nv_bfloat16* __restrict__ Ahi,
              const __nv_bfloat16* __restrict__ Alo,
              const __nv_bfloat16* __restrict__ Bhi,
              const __nv_bfloat16* __restrict__ Blo,
              float* __restrict__ C, int M, int N, int K,
              const float* __restrict__ bias1, const float* __restrict__ bias2)
{
    __shared__ __nv_bfloat16 As[2][2][128][16];
    __shared__ __nv_bfloat16 Bs[2][2][128][16];

    const int tid  = threadIdx.x;
    const int wid  = tid >> 5;
    const int lane = tid & 31;
    const int gid  = lane >> 2;
    const int tig  = lane & 3;
    const int wm   = wid >> 2;
    const int wn   = wid & 3;
    const int bm   = blockIdx.y * 128;
    const int bn   = blockIdx.x * 128;
    const int KC   = K >> 5;
    const int total = 3 * KC;

    float acc[4][4][4];
#pragma unroll
    for (int mt = 0; mt < 4; mt++)
#pragma unroll
        for (int nt = 0; nt < 4; nt++)
#pragma unroll
            for (int r = 0; r < 4; r++) acc[mt][nt][r] = 0.f;

    const int srow = tid >> 1;
    const int shalf = tid & 1;

    auto issue = [&](int it) {
        int p  = it / KC;
        int kc = (it - p * KC) << 5;
        const __nv_bfloat16* Asrc = (p == 1) ? Alo : Ahi;
        const __nv_bfloat16* Bsrc = (p == 2) ? Blo : Bhi;
        int buf = it & 1;
#pragma unroll
        for (int kh = 0; kh < 2; kh++) {
            const __nv_bfloat16* ga =
                Asrc + (size_t)(bm + srow) * K + kc + kh * 16 + shalf * 8;
            cpa16((unsigned)__cvta_generic_to_shared(&As[buf][kh][srow][shalf * 8]), ga);
            const __nv_bfloat16* gb =
                Bsrc + (size_t)(bn + srow) * K + kc + kh * 16 + shalf * 8;
            cpa16((unsigned)__cvta_generic_to_shared(&Bs[buf][kh][srow][shalf * 8]), gb);
        }
        cp_commit();
    };

    const int arow = (wm << 6) + (lane & 15);
    const int acol = (lane >> 4) << 3;
    const int brow = (wn << 5) + (lane & 7);
    const int bcol = ((lane >> 3) & 1) << 3;

    issue(0);
    for (int it = 0; it < total; it++) {
        if (it + 1 < total) { issue(it + 1); cp_wait1(); }
        else                { cp_wait0(); }
        __syncthreads();
        const int buf = it & 1;
#pragma unroll
        for (int kh = 0; kh < 2; kh++) {
            unsigned a[4][4], b[4][2];
#pragma unroll
            for (int mt = 0; mt < 4; mt++)
                ldsm_x4(a[mt], (unsigned)__cvta_generic_to_shared(
                    &As[buf][kh][arow + (mt << 4)][acol]));
#pragma unroll
            for (int nt = 0; nt < 4; nt++)
                ldsm_x2(b[nt], (unsigned)__cvta_generic_to_shared(
                    &Bs[buf][kh][brow + (nt << 3)][bcol]));
#pragma unroll
            for (int mt = 0; mt < 4; mt++)
#pragma unroll
                for (int nt = 0; nt < 4; nt++)
                    mma16816(acc[mt][nt], a[mt], b[nt]);
        }
        __syncthreads();
    }

#pragma unroll
    for (int mt = 0; mt < 4; mt++)
#pragma unroll
        for (int nt = 0; nt < 4; nt++)
#pragma unroll
            for (int rp = 0; rp < 2; rp++) {
                int row = bm + (wm << 6) + (mt << 4) + gid + (rp << 3);
                int col = bn + (wn << 5) + (nt << 3) + (tig << 1);
                float v0 = acc[mt][nt][rp * 2];
                float v1 = acc[mt][nt][rp * 2 + 1];
                if (EPI == 1) {
                    v0 += __ldg(bias1 + col) + __ldg(bias2 + col);
                    v1 += __ldg(bias1 + col + 1) + __ldg(bias2 + col + 1);
                }
                if (EPI == 2) { v0 = tanhf(v0); v1 = tanhf(v1); }
                float2 o; o.x = v0; o.y = v1;
                *(float2*)(C + (size_t)row * N + col) = o;
            }
}

// ---------------- persistent LSTM layer ----------------
// grid = 128 blocks, 256 threads. Block owns d0..d0+7 (all 4 gates, 32 N rows),
// all 64 batches. Weights (hi+lo, 128KB) resident in smem for all 32 steps.
// Warp w: m-tile (w&3), n-half (w>>2); full-K accumulation (no reduction).
// smem: ws 131072 | hs 32768 | red 8448 | cs 2048  = 174336 B
#define LSTM_SMEM 174336

__device__ __forceinline__ void grid_bar(unsigned target)
{
    __threadfence();
    __syncthreads();
    if (threadIdx.x == 0) {
        atomicAdd(&g_cnt, 1u);
        while (*((volatile unsigned*)&g_cnt) < target) __nanosleep(64);
        __threadfence();
    }
    __syncthreads();
}

__global__ __launch_bounds__(256, 1)
void lstm_layer_persist(const __nv_bfloat16* __restrict__ h0h,
                        const __nv_bfloat16* __restrict__ h0l,
                        const __nv_bfloat16* __restrict__ whi,
                        const __nv_bfloat16* __restrict__ wlo,
                        const float* __restrict__ c0,
                        const float* __restrict__ xg,
                        float* __restrict__ hseq,
                        __nv_bfloat16* __restrict__ shh,
                        __nv_bfloat16* __restrict__ shl,
                        float* __restrict__ cn_out)
{
    extern __shared__ char smem[];
    float* red = (float*)(smem + 163840);
    float* cs  = (float*)(smem + 172288);

    const int tid  = threadIdx.x;
    const int wid  = tid >> 5;
    const int lane = tid & 31;
    const int gid  = lane >> 2;
    const int tig  = lane & 3;
    const int mt   = wid & 3;       // m-tile (16 batches)
    const int nh   = wid >> 2;      // n-half (16 cols)
    const int d0   = blockIdx.x << 3;

    const unsigned WS = (unsigned)__cvta_generic_to_shared(smem);
    const unsigned HS = WS + 131072;

    // ---- preload weights (hi+lo) into smem: [hl][k16][r][16] ----
#pragma unroll
    for (int i = 0; i < 32; i++) {
        int id   = tid + (i << 8);          // 0..8191
        int half = id & 1;
        int r    = (id >> 1) & 31;
        int k16  = (id >> 6) & 63;
        int hl   = id >> 12;
        int grow = ((r >> 3) << 10) + d0 + (r & 7);
        const __nv_bfloat16* src =
            (hl ? wlo : whi) + (size_t)grow * D_ + (k16 << 4) + (half << 3);
        cpa16(WS + hl * 65536 + (k16 << 10) + (r << 5) + (half << 4), src);
    }
    cp_commit();
    // c0 slice -> smem
#pragma unroll
    for (int j = 0; j < 2; j++) {
        int pid = tid + (j << 8);
        cs[pid] = __ldg(c0 + (size_t)(pid >> 3) * D_ + d0 + (pid & 7));
    }
    cp_wait0();
    __syncthreads();

    // fragment smem offsets (bytes)
    const unsigned aoff  = (unsigned)(((mt << 4) + (lane & 15)) * 32 + (((lane >> 4) & 1) << 4));
    const unsigned boff0 = (unsigned)(((nh << 4) + (lane & 7)) * 32 + (((lane >> 3) & 1) << 4));
    const unsigned boff1 = boff0 + 8 * 32;

    for (int t = 0; t < T_; t++) {
        const __nv_bfloat16* ah = t ? shh + (size_t)(t - 1) * BD_ : h0h;
        const __nv_bfloat16* al = t ? shl + (size_t)(t - 1) * BD_ : h0l;
        const float* xgt = xg + (size_t)t * B_ * D4_;

        // prefetch gate biases from xg
        float xv[2][4];
#pragma unroll
        for (int j = 0; j < 2; j++) {
            int pid = tid + (j << 8);
            int b = pid >> 3, dd = pid & 7;
#pragma unroll
            for (int g = 0; g < 4; g++)
                xv[j][g] = __ldg(xgt + (size_t)b * D4_ + (g << 10) + d0 + dd);
        }

        float acc[2][4];
#pragma unroll
        for (int nt = 0; nt < 2; nt++)
#pragma unroll
            for (int r = 0; r < 4; r++) acc[nt][r] = 0.f;

        // stage h chunk (BK=64: 4 k16, hi+lo) into hs[buf]
        auto issue = [&](int ck) {
            int buf = ck & 1;
#pragma unroll
            for (int i = 0; i < 4; i++) {
                int id   = tid + (i << 8);     // 0..1023
                int half = id & 1;
                int row  = (id >> 1) & 63;
                int k16l = (id >> 7) & 3;
                int hl   = id >> 9;
                const __nv_bfloat16* src =
                    (hl ? al : ah) + (size_t)row * D_ + (ck << 6) + (k16l << 4) + (half << 3);
                cpa16(HS + buf * 16384 + hl * 8192 + (k16l << 11) + (row << 5) + (half << 4), src);
            }
            cp_commit();
        };

        issue(0);
        for (int ck = 0; ck < 16; ck++) {
            if (ck < 15) { issue(ck + 1); cp_wait1(); }
            else         { cp_wait0(); }
            __syncthreads();
            const unsigned hb = HS + (unsigned)((ck & 1) * 16384);
#pragma unroll
            for (int k16l = 0; k16l < 4; k16l++) {
                unsigned ahi[4], alo[4], bh0[2], bh1[2], bl0[2], bl1[2];
                ldsm_x4(ahi, hb + (k16l << 11) + aoff);
                ldsm_x4(alo, hb + 8192 + (k16l << 11) + aoff);
                unsigned kb = WS + (unsigned)((((ck << 2) + k16l)) << 10);
                ldsm_x2(bh0, kb + boff0);
                ldsm_x2(bh1, kb + boff1);
                ldsm_x2(bl0, kb + 65536 + boff0);
                ldsm_x2(bl1, kb + 65536 + boff1);
                mma16816(acc[0], ahi, bh0);
                mma16816(acc[1], ahi, bh1);
                mma16816(acc[0], alo, bh0);
                mma16816(acc[1], alo, bh1);
                mma16816(acc[0], ahi, bl0);
                mma16816(acc[1], ahi, bl1);
            }
            __syncthreads();
        }

        // stage gates into red[b*33 + n]
#pragma unroll
        for (int nt = 0; nt < 2; nt++)
#pragma unroll
            for (int r = 0; r < 4; r++) {
                int b = (mt << 4) + gid + ((r >> 1) << 3);
                int n = (nh << 4) + (nt << 3) + (tig << 1) + (r & 1);
                red[b * 33 + n] = acc[nt][r];
            }
        __syncthreads();

        // pointwise
#pragma unroll
        for (int j = 0; j < 2; j++) {
            int pid = tid + (j << 8);
            int b = pid >> 3, dd = pid & 7;
            float ig = red[b * 33 +  0 + dd] + xv[j][0];
            float fg = red[b * 33 +  8 + dd] + xv[j][1];
            float gg = red[b * 33 + 16 + dd] + xv[j][2];
            float og = red[b * 33 + 24 + dd] + xv[j][3];
            float ci = cs[pid];
            float i_ = 1.f / (1.f + __expf(-ig));
            float f_ = 1.f / (1.f + __expf(-fg));
            float o_ = 1.f / (1.f + __expf(-og));
            float cn = f_ * ci + i_ * tanhf(gg);
            float hn = o_ * tanhf(cn);
            cs[pid] = cn;
            size_t idx = (size_t)t * BD_ + (size_t)b * D_ + d0 + dd;
            hseq[idx] = hn;
            float hh = __bfloat162float(__float2bfloat16(hn));
            shh[idx] = __float2bfloat16(hh);
            shl[idx] = __float2bfloat16(hn - hh);
        }
        __syncthreads();   // red reuse safety next step

        if (t < T_ - 1) grid_bar((unsigned)(t + 1) * gridDim.x);
    }

    // final c
#pragma unroll
    for (int j = 0; j < 2; j++) {
        int pid = tid + (j << 8);
        cn_out[(size_t)(pid >> 3) * D_ + d0 + (pid & 7)] = cs[pid];
    }

    // end handshake: last block resets barrier counters for next launch/replay
    __threadfence();
    __syncthreads();
    if (tid == 0) {
        unsigned d = atomicAdd(&g_done, 1u) + 1;
        if (d == gridDim.x) {
            g_cnt = 0;
            g_done = 0;
            __threadfence();
        }
    }
}

// ---------------- attention ----------------
__global__ __launch_bounds__(256)
void attn_kernel(const float* __restrict__ q,
                 const float* __restrict__ ctx,
                 const float* __restrict__ x,
                 __nv_bfloat16* __restrict__ cath,
                 __nv_bfloat16* __restrict__ catl,
                 float* __restrict__ attn_out)
{
    const int b = blockIdx.x;
    const int t = blockIdx.y;
    const int tb = t * B_ + b;
    __shared__ float qs[D_];
    __shared__ float sc[S_];

    const int tid = threadIdx.x;
    const int warp = tid >> 5, lane = tid & 31;

    ((float4*)qs)[tid] = ((const float4*)(q + (size_t)tb * D_))[tid];
    __syncthreads();

#pragma unroll
    for (int si = 0; si < 8; si++) {
        int s = warp * 8 + si;
        const float4* crow = (const float4*)(ctx + (size_t)(s * B_ + b) * D_);
        float sum = 0.f;
#pragma unroll
        for (int i = 0; i < 8; i++) {
            float4 cv = crow[lane + 32 * i];
            float4 qv = ((const float4*)qs)[lane + 32 * i];
            sum = fmaf(cv.x, qv.x, sum);
            sum = fmaf(cv.y, qv.y, sum);
            sum = fmaf(cv.z, qv.z, sum);
            sum = fmaf(cv.w, qv.w, sum);
        }
#pragma unroll
        for (int off = 16; off; off >>= 1)
            sum += __shfl_down_sync(0xffffffffu, sum, off);
        if (lane == 0) sc[s] = sum;
    }
    __syncthreads();

    if (warp == 0) {
        float v0 = sc[lane], v1 = sc[lane + 32];
        float m = fmaxf(v0, v1);
#pragma unroll
        for (int off = 16; off; off >>= 1)
            m = fmaxf(m, __shfl_xor_sync(0xffffffffu, m, off));
        float e0 = __expf(v0 - m), e1 = __expf(v1 - m);
        float ssum = e0 + e1;
#pragma unroll
        for (int off = 16; off; off >>= 1)
            ssum += __shfl_xor_sync(0xffffffffu, ssum, off);
        float inv = 1.f / ssum;
        sc[lane] = e0 * inv;
        sc[lane + 32] = e1 * inv;
    }
    __syncthreads();

    float4 accv = make_float4(0.f, 0.f, 0.f, 0.f);
    for (int s = 0; s < S_; s++) {
        float a = sc[s];
        float4 cv = ((const float4*)(ctx + (size_t)(s * B_ + b) * D_))[tid];
        accv.x = fmaf(a, cv.x, accv.x);
        accv.y = fmaf(a, cv.y, accv.y);
        accv.z = fmaf(a, cv.z, accv.z);
        accv.w = fmaf(a, cv.w, accv.w);
    }
    __nv_bfloat162* ch = (__nv_bfloat162*)(cath + (size_t)tb * 2 * D_);
    __nv_bfloat162* cl = (__nv_bfloat162*)(catl + (size_t)tb * 2 * D_);
    split_store4(accv, ch + tid * 2, cl + tid * 2);
    float4 xv = ((const float4*)(x + (size_t)tb * D_))[tid];
    split_store4(xv, ch + D_ / 2 + tid * 2, cl + D_ / 2 + tid * 2);

    if (t == T_ - 1 && tid < S_) attn_out[b * S_ + tid] = sc[tid];
}

// ---------------- launch ----------------
extern "C" void kernel_launch(void* const* d_in, const int* in_sizes, int n_in,
                              void* d_out, int out_size)
{
    (void)in_sizes; (void)n_in; (void)out_size;

    const int*   input = (const int*)  d_in[0];
    const float* h0    = (const float*)d_in[1];
    const float* c0    = (const float*)d_in[2];
    const float* ctx   = (const float*)d_in[3];
    const float* emb   = (const float*)d_in[5];
    const float* wih0  = (const float*)d_in[6];
    const float* whh0  = (const float*)d_in[7];
    const float* bih0  = (const float*)d_in[8];
    const float* bhh0  = (const float*)d_in[9];
    const float* wih1  = (const float*)d_in[10];
    const float* whh1  = (const float*)d_in[11];
    const float* bih1  = (const float*)d_in[12];
    const float* bhh1  = (const float*)d_in[13];
    const float* w_in  = (const float*)d_in[14];
    const float* w_out = (const float*)d_in[15];

    float* out      = (float*)d_out;
    float* out_hn   = out + (size_t)TB_ * D_;
    float* out_cn   = out_hn + (size_t)2 * BD_;
    float* out_attn = out_cn + (size_t)2 * BD_;

    float *xg, *x1, *x2, *q;
    cudaGetSymbolAddress((void**)&xg, g_xg);
    cudaGetSymbolAddress((void**)&x1, g_x1);
    cudaGetSymbolAddress((void**)&x2, g_x2);
    cudaGetSymbolAddress((void**)&q,  g_q);

    __nv_bfloat16 *x0h, *x0l, *sh, *sl, *h0h, *h0l, *cath, *catl;
    __nv_bfloat16 *whhh0, *whhl0, *whhh1, *whhl1;
    __nv_bfloat16 *wihh0, *wihl0, *wihh1, *wihl1, *winh, *winl, *wouth, *woutl;
    cudaGetSymbolAddress((void**)&x0h, g_x0h);   cudaGetSymbolAddress((void**)&x0l, g_x0l);
    cudaGetSymbolAddress((void**)&sh,  g_sh);    cudaGetSymbolAddress((void**)&sl,  g_sl);
    cudaGetSymbolAddress((void**)&h0h, g_h0h);   cudaGetSymbolAddress((void**)&h0l, g_h0l);
    cudaGetSymbolAddress((void**)&cath, g_cath); cudaGetSymbolAddress((void**)&catl, g_catl);
    cudaGetSymbolAddress((void**)&whhh0, g_whhh0); cudaGetSymbolAddress((void**)&whhl0, g_whhl0);
    cudaGetSymbolAddress((void**)&whhh1, g_whhh1); cudaGetSymbolAddress((void**)&whhl1, g_whhl1);
    cudaGetSymbolAddress((void**)&wihh0, g_wihh0); cudaGetSymbolAddress((void**)&wihl0, g_wihl0);
    cudaGetSymbolAddress((void**)&wihh1, g_wihh1); cudaGetSymbolAddress((void**)&wihl1, g_wihl1);
    cudaGetSymbolAddress((void**)&winh,  g_winh);  cudaGetSymbolAddress((void**)&winl,  g_winl);
    cudaGetSymbolAddress((void**)&wouth, g_wouth); cudaGetSymbolAddress((void**)&woutl, g_woutl);

    static int smem_set = 0;
    if (!smem_set) {
        cudaFuncSetAttribute(lstm_layer_persist,
                             cudaFuncAttributeMaxDynamicSharedMemorySize, LSTM_SMEM);
        smem_set = 1;
    }

    const size_t BD = (size_t)BD_;

    // 0) weight splits
    split_kernel<<<4096, 256>>>(whh0, whhh0, whhl0, D4_ * D_ / 4);
    split_kernel<<<4096, 256>>>(whh1, whhh1, whhl1, D4_ * D_ / 4);
    split_kernel<<<4096, 256>>>(wih0, wihh0, wihl0, D4_ * D_ / 4);
    split_kernel<<<4096, 256>>>(wih1, wihh1, wihl1, D4_ * D_ / 4);
    split_kernel<<<1024, 256>>>(w_in, winh, winl, D_ * D_ / 4);
    split_kernel<<<2048, 256>>>(w_out, wouth, woutl, D_ * 2 * D_ / 4);

    // 1) embedding -> bf16 hi/lo
    embed_kernel<<<TB_, 256>>>(input, emb, x0h, x0l);

    // 2) layer 0
    hgemm_nt<1><<<dim3(D4_ / 128, TB_ / 128), 256>>>(
        x0h, x0l, wihh0, wihl0, xg, TB_, D4_, D_, bih0, bhh0);
    split_kernel<<<64, 256>>>(h0, h0h, h0l, (int)(BD / 4));
    lstm_layer_persist<<<128, 256, LSTM_SMEM>>>(
        h0h, h0l, whhh0, whhl0, c0, xg, x1, sh, sl, out_cn);
    cudaMemcpyAsync(out_hn, x1 + (size_t)(T_ - 1) * BD, BD * sizeof(float),
                    cudaMemcpyDeviceToDevice, 0);

    // 3) layer 1
    hgemm_nt<1><<<dim3(D4_ / 128, TB_ / 128), 256>>>(
        sh, sl, wihh1, wihl1, xg, TB_, D4_, D_, bih1, bhh1);
    split_kernel<<<64, 256>>>(h0 + BD, h0h, h0l, (int)(BD / 4));
    lstm_layer_persist<<<128, 256, LSTM_SMEM>>>(
        h0h, h0l, whhh1, whhl1, c0 + BD, xg, x2, sh, sl, out_cn + BD);
    cudaMemcpyAsync(out_hn + BD, x2 + (size_t)(T_ - 1) * BD, BD * sizeof(float),
                    cudaMemcpyDeviceToDevice, 0);

    // 4) attention
    hgemm_nt<0><<<dim3(D_ / 128, TB_ / 128), 256>>>(
        sh, sl, winh, winl, q, TB_, D_, D_, nullptr, nullptr);
    attn_kernel<<<dim3(B_, T_), 256>>>(q, ctx, x2, cath, catl, out_attn);

    // 5) out = tanh(cat @ w_out^T)
    hgemm_nt<2><<<dim3(D_ / 128, TB_ / 128), 256>>>(
        cath, catl, wouth, woutl, out, TB_, D_, 2 * D_, nullptr, nullptr);
}